// round 5
// baseline (speedup 1.0000x reference)
#include <cuda_runtime.h>
#include <cstdint>

#define N_NODES 50000
#define E_EDGES 1600000
#define M_TOTAL (E_EDGES + N_NODES)
#define TILE_M  64
#define NT      ((M_TOTAL + TILE_M - 1) / TILE_M)   // 25782
#define GRID_MSG 296

__device__ float g_agg[N_NODES * 64];
__device__ int g_ei_is64;
__device__ int g_tile;

// ---------------------------------------------------------------------------
__device__ __forceinline__ uint32_t f2tf(float a) {
    uint32_t r; asm("cvt.rna.tf32.f32 %0, %1;" : "=r"(r) : "f"(a)); return r;
}
__device__ __forceinline__ float2 splt(float v) {
    float hi = __uint_as_float(f2tf(v));
    float lo = __uint_as_float(f2tf(v - hi));
    return make_float2(hi, lo);
}
__device__ __forceinline__ void mma8(float acc[4],
    uint32_t a0, uint32_t a1, uint32_t a2, uint32_t a3,
    uint32_t b0, uint32_t b1)
{
    asm volatile(
        "mma.sync.aligned.m16n8k8.row.col.f32.tf32.tf32.f32 "
        "{%0,%1,%2,%3}, {%4,%5,%6,%7}, {%8,%9}, {%0,%1,%2,%3};"
        : "+f"(acc[0]), "+f"(acc[1]), "+f"(acc[2]), "+f"(acc[3])
        : "r"(a0), "r"(a1), "r"(a2), "r"(a3), "r"(b0), "r"(b1));
}
#define FU(v) __float_as_uint(v)

// ---------------------------------------------------------------------------
__global__ void k_detect(const int* __restrict__ ei_raw) {
    __shared__ int any_nonzero;
    if (threadIdx.x == 0) any_nonzero = 0;
    __syncthreads();
    int w = ei_raw[2 * threadIdx.x + 1];
    if (w != 0) atomicOr(&any_nonzero, 1);
    __syncthreads();
    if (threadIdx.x == 0) g_ei_is64 = any_nonzero ? 0 : 1;
}

__global__ void k_zero() {
    int i = blockIdx.x * blockDim.x + threadIdx.x;
    if (i == 0) g_tile = 0;
    if (i < N_NODES * 64 / 4)
        ((float4*)g_agg)[i] = make_float4(0.f, 0.f, 0.f, 0.f);
}

// ---------------------------------------------------------------------------
// SMEM layout, float2 (hi,lo) pairs for all MMA operands.
//   WT1 [n=64][k stride 41]  (W1^T, K padded 35->40, rows 35..39 = 0)
//   WT2 [n=64][k stride 65]  (W2^T, K=64)
//   MSG [m=64][k stride 41]  (message tile; also reused as fp32 sOut stride 66)
//   H1  [m=64][k stride 65]
// Strides chosen so the 8 mma lane-groups land on distinct 4B banks.
// ---------------------------------------------------------------------------
#define OWT1  0
#define OWT2  (OWT1 + 64 * 41)          // f2 units
#define OMSG  (OWT2 + 64 * 65)
#define OH1   (OMSG + 64 * 41)
#define OEND  (OH1 + 64 * 65)
#define OB1   (OEND * 2)                // float units from here
#define OB2   (OB1 + 64)
#define ODST  (OB2 + 64)                // 64 ints
#define OTI   (ODST + 64)
#define SMEM_MSG_BYTES ((OTI + 1) * 4 + 16)

__global__ __launch_bounds__(128) void k_msg(
    const float* __restrict__ x, const float* __restrict__ pos,
    const void* __restrict__ ei_raw,
    const float* __restrict__ W1, const float* __restrict__ bias1,
    const float* __restrict__ W2, const float* __restrict__ bias2)
{
    extern __shared__ float smf[];
    float2* WT1 = (float2*)smf + OWT1;
    float2* WT2 = (float2*)smf + OWT2;
    float2* MSG = (float2*)smf + OMSG;
    float2* H1  = (float2*)smf + OH1;
    float*  sOut = (float*)((float2*)smf + OMSG);   // stride 66 floats, 64*66 <= 64*41*2
    float*  sB1 = smf + OB1;
    float*  sB2 = smf + OB2;
    int*    sDst = (int*)(smf + ODST);
    volatile int* sTi = (volatile int*)(smf + OTI);

    const int tid = threadIdx.x;
    const int wid = tid >> 5;
    const int lid = tid & 31;
    const int g   = lid >> 2;       // lane group 0..7
    const int t4  = lid & 3;

    // ---- stage split weights (once per CTA) ----
    for (int i = tid; i < 64 * 40; i += 128) {
        int k = i >> 6, n = i & 63;
        WT1[n * 41 + k] = splt(k < 35 ? W1[k * 64 + n] : 0.f);
    }
    for (int i = tid; i < 64 * 64; i += 128) {
        int k = i >> 6, n = i & 63;
        WT2[n * 65 + k] = splt(W2[k * 64 + n]);
    }
    if (tid < 64) sB1[tid] = bias1[tid];
    else if (tid < 128) sB2[tid - 64] = bias2[tid - 64];
    __syncthreads();

    const int is64 = g_ei_is64;
    const int r0 = wid * 16 + g;    // row of a0/a2 & c0/c1 within tile

    for (;;) {
        if (tid == 0) *sTi = atomicAdd(&g_tile, 1);
        __syncthreads();            // also fences prev-iter atomics vs MSG reuse
        const int t = *sTi;
        if (t >= NT) break;

        // ---- gather: thread pair per message row ----
        {
            int r = tid >> 1, h = tid & 1;
            int m = t * TILE_M + r;
            int src = 0, dst = -1;
            if (m < E_EDGES) {
                if (is64) { const long long* e = (const long long*)ei_raw;
                            src = (int)e[m]; dst = (int)e[E_EDGES + m]; }
                else      { const int* e = (const int*)ei_raw;
                            src = e[m]; dst = e[E_EDGES + m]; }
                if ((unsigned)src >= N_NODES) src = 0;
                if ((unsigned)dst >= N_NODES) dst = 0;
            } else if (m < M_TOTAL) { src = m - E_EDGES; dst = src; }
            if (h == 0) sDst[r] = dst;

            const float4* xp = (const float4*)(x + (size_t)src * 32 + h * 16);
            float2* mrow = MSG + r * 41 + h * 16;
            #pragma unroll
            for (int q = 0; q < 4; q++) {
                float4 v = __ldg(xp + q);
                mrow[q * 4 + 0] = splt(v.x);
                mrow[q * 4 + 1] = splt(v.y);
                mrow[q * 4 + 2] = splt(v.z);
                mrow[q * 4 + 3] = splt(v.w);
            }
            if (h == 1) {
                float p0 = 0.f, p1 = 0.f, p2 = 0.f;
                if (dst >= 0 && m < E_EDGES) {
                    p0 = pos[src * 3 + 0] - pos[dst * 3 + 0];
                    p1 = pos[src * 3 + 1] - pos[dst * 3 + 1];
                    p2 = pos[src * 3 + 2] - pos[dst * 3 + 2];
                }
                float2* prow = MSG + r * 41;
                prow[32] = splt(p0); prow[33] = splt(p1); prow[34] = splt(p2);
                prow[35] = make_float2(0.f, 0.f); prow[36] = make_float2(0.f, 0.f);
                prow[37] = make_float2(0.f, 0.f); prow[38] = make_float2(0.f, 0.f);
                prow[39] = make_float2(0.f, 0.f);
            }
        }
        __syncthreads();

        float acc[8][4];

        // ---- GEMM1: tile(64x40) @ W1p(40x64), 5 k-chunks, 3-pass split ----
        #pragma unroll
        for (int nb = 0; nb < 8; nb++) {
            int c0 = nb * 8 + 2 * t4;
            acc[nb][0] = sB1[c0];     acc[nb][1] = sB1[c0 + 1];
            acc[nb][2] = sB1[c0];     acc[nb][3] = sB1[c0 + 1];
        }
        for (int kc = 0; kc < 5; kc++) {
            const int kb = kc * 8 + t4;
            float2 A0 = MSG[r0 * 41 + kb];
            float2 A1 = MSG[(r0 + 8) * 41 + kb];
            float2 A2 = MSG[r0 * 41 + kb + 4];
            float2 A3 = MSG[(r0 + 8) * 41 + kb + 4];
            #pragma unroll
            for (int nb = 0; nb < 8; nb++) {
                float2 B0 = WT1[(nb * 8 + g) * 41 + kb];
                float2 B1 = WT1[(nb * 8 + g) * 41 + kb + 4];
                mma8(acc[nb], FU(A0.x), FU(A1.x), FU(A2.x), FU(A3.x), FU(B0.x), FU(B1.x));
                mma8(acc[nb], FU(A0.y), FU(A1.y), FU(A2.y), FU(A3.y), FU(B0.x), FU(B1.x));
                mma8(acc[nb], FU(A0.x), FU(A1.x), FU(A2.x), FU(A3.x), FU(B0.y), FU(B1.y));
            }
        }

        // ---- epilogue 1: relu, split -> H1 ----
        #pragma unroll
        for (int nb = 0; nb < 8; nb++) {
            int c0 = nb * 8 + 2 * t4;
            H1[r0 * 65 + c0]           = splt(fmaxf(acc[nb][0], 0.f));
            H1[r0 * 65 + c0 + 1]       = splt(fmaxf(acc[nb][1], 0.f));
            H1[(r0 + 8) * 65 + c0]     = splt(fmaxf(acc[nb][2], 0.f));
            H1[(r0 + 8) * 65 + c0 + 1] = splt(fmaxf(acc[nb][3], 0.f));
        }
        __syncthreads();

        // ---- GEMM2: H1(64x64) @ W2p(64x64), 8 k-chunks, 3-pass split ----
        #pragma unroll
        for (int nb = 0; nb < 8; nb++) {
            int c0 = nb * 8 + 2 * t4;
            acc[nb][0] = sB2[c0];     acc[nb][1] = sB2[c0 + 1];
            acc[nb][2] = sB2[c0];     acc[nb][3] = sB2[c0 + 1];
        }
        for (int kc = 0; kc < 8; kc++) {
            const int kb = kc * 8 + t4;
            float2 A0 = H1[r0 * 65 + kb];
            float2 A1 = H1[(r0 + 8) * 65 + kb];
            float2 A2 = H1[r0 * 65 + kb + 4];
            float2 A3 = H1[(r0 + 8) * 65 + kb + 4];
            #pragma unroll
            for (int nb = 0; nb < 8; nb++) {
                float2 B0 = WT2[(nb * 8 + g) * 65 + kb];
                float2 B1 = WT2[(nb * 8 + g) * 65 + kb + 4];
                mma8(acc[nb], FU(A0.x), FU(A1.x), FU(A2.x), FU(A3.x), FU(B0.x), FU(B1.x));
                mma8(acc[nb], FU(A0.y), FU(A1.y), FU(A2.y), FU(A3.y), FU(B0.x), FU(B1.x));
                mma8(acc[nb], FU(A0.x), FU(A1.x), FU(A2.x), FU(A3.x), FU(B0.y), FU(B1.y));
            }
        }

        // ---- epilogue 2: relu -> sOut (overlaps MSG; GEMM1 reads all done) ----
        #pragma unroll
        for (int nb = 0; nb < 8; nb++) {
            int c0 = nb * 8 + 2 * t4;
            sOut[r0 * 66 + c0]           = fmaxf(acc[nb][0], 0.f);
            sOut[r0 * 66 + c0 + 1]       = fmaxf(acc[nb][1], 0.f);
            sOut[(r0 + 8) * 66 + c0]     = fmaxf(acc[nb][2], 0.f);
            sOut[(r0 + 8) * 66 + c0 + 1] = fmaxf(acc[nb][3], 0.f);
        }
        __syncthreads();

        // ---- coalesced predicated max scatter: warp per message ----
        for (int m = wid; m < TILE_M; m += 4) {
            int dst = sDst[m];
            if (dst < 0) continue;
            float v0 = sOut[m * 66 + lid];
            float v1 = sOut[m * 66 + 32 + lid];
            int* ap = (int*)g_agg + (size_t)dst * 64;
            if (v0 > 0.f) atomicMax(ap + lid,      __float_as_int(v0));
            if (v1 > 0.f) atomicMax(ap + 32 + lid, __float_as_int(v1));
        }
        // next-iteration top __syncthreads orders atomics before MSG overwrite
    }
}

// ---------------------------------------------------------------------------
// Kernel 2: out = agg @ Wg + bg    [50000,64] x [64,128]
// ---------------------------------------------------------------------------
#define SMO_A 0
#define SMO_W (64 * 68)
#define SMEM_OUT_BYTES ((64 * 68 + 64 * 128) * 4)

__global__ __launch_bounds__(128) void k_out(
    const float* __restrict__ Wg, const float* __restrict__ bg,
    float* __restrict__ out)
{
    extern __shared__ float sm[];
    float* sA = sm + SMO_A;
    float* sW = sm + SMO_W;
    const int tid = threadIdx.x;
    const int nbase = blockIdx.x * 64;

    {
        float4* dst4 = (float4*)sW;
        const float4* src4 = (const float4*)Wg;
        for (int i = tid; i < 64 * 32; i += 128) dst4[i] = __ldg(src4 + i);
    }
    for (int idx = tid; idx < 64 * 16; idx += 128) {
        int rr = idx >> 4, c4 = idx & 15;
        float4 v = make_float4(0.f, 0.f, 0.f, 0.f);
        if (nbase + rr < N_NODES)
            v = *(const float4*)(g_agg + (size_t)(nbase + rr) * 64 + c4 * 4);
        *(float4*)(sA + rr * 68 + c4 * 4) = v;
    }
    __syncthreads();

    const int tx = tid & 15;
    const int ty = tid >> 4;
    const int fbase = tx * 8;

    float acc[8][8];
    float bj[8];
    #pragma unroll
    for (int j = 0; j < 8; j++) bj[j] = __ldg(&bg[fbase + j]);
    #pragma unroll
    for (int i = 0; i < 8; i++)
        #pragma unroll
        for (int j = 0; j < 8; j++) acc[i][j] = bj[j];

    for (int k4 = 0; k4 < 16; k4++) {
        const int k0 = k4 * 4;
        float4 wv[4][2];
        #pragma unroll
        for (int kk = 0; kk < 4; kk++) {
            wv[kk][0] = *(const float4*)(sW + (k0 + kk) * 128 + fbase);
            wv[kk][1] = *(const float4*)(sW + (k0 + kk) * 128 + fbase + 4);
        }
        #pragma unroll
        for (int i = 0; i < 8; i++) {
            float4 av = *(const float4*)(sA + (ty + 8 * i) * 68 + k0);
            float a4[4] = {av.x, av.y, av.z, av.w};
            #pragma unroll
            for (int kk = 0; kk < 4; kk++) {
                const float* w = &wv[kk][0].x;
                #pragma unroll
                for (int j = 0; j < 8; j++)
                    acc[i][j] = fmaf(a4[kk], w[j], acc[i][j]);
            }
        }
    }

    #pragma unroll
    for (int i = 0; i < 8; i++) {
        int n = nbase + ty + 8 * i;
        if (n < N_NODES) {
            float4 v0, v1;
            v0.x = acc[i][0]; v0.y = acc[i][1]; v0.z = acc[i][2]; v0.w = acc[i][3];
            v1.x = acc[i][4]; v1.y = acc[i][5]; v1.z = acc[i][6]; v1.w = acc[i][7];
            *(float4*)(out + (size_t)n * 128 + fbase)     = v0;
            *(float4*)(out + (size_t)n * 128 + fbase + 4) = v1;
        }
    }
}

// ---------------------------------------------------------------------------
extern "C" void kernel_launch(void* const* d_in, const int* in_sizes, int n_in,
                              void* d_out, int out_size) {
    const float* x   = (const float*)d_in[0];
    const float* pos = (const float*)d_in[1];
    const void*  ei  = d_in[2];
    const float* W1  = (const float*)d_in[3];
    const float* b1  = (const float*)d_in[4];
    const float* W2  = (const float*)d_in[5];
    const float* b2  = (const float*)d_in[6];
    const float* Wg  = (const float*)d_in[7];
    const float* bg  = (const float*)d_in[8];
    float* out = (float*)d_out;

    cudaFuncSetAttribute(k_msg, cudaFuncAttributeMaxDynamicSharedMemorySize, SMEM_MSG_BYTES);
    cudaFuncSetAttribute(k_out, cudaFuncAttributeMaxDynamicSharedMemorySize, SMEM_OUT_BYTES);

    k_detect<<<1, 1024>>>((const int*)ei);
    k_zero<<<(N_NODES * 64 / 4 + 255) / 256, 256>>>();
    k_msg<<<GRID_MSG, 128, SMEM_MSG_BYTES>>>(x, pos, ei, W1, b1, W2, b2);
    k_out<<<(N_NODES + 63) / 64, 128, SMEM_OUT_BYTES>>>(Wg, bg, out);
}

// round 6
// speedup vs baseline: 2.4775x; 2.4775x over previous
#include <cuda_runtime.h>
#include <cuda_bf16.h>
#include <cstdint>

#define N_NODES 50000
#define E_EDGES 1600000
#define M_TOTAL (E_EDGES + N_NODES)
#define TILE_E 128
#define NT ((M_TOTAL + TILE_E - 1) / TILE_E)   // 12891

__device__ float g_agg[N_NODES * 64];
__device__ int g_ei_is64;

// ---------------------------------------------------------------------------
// smem layout (bytes). bf16 arrays addressed as 32-bit words (bf16x2 pairs).
//   MSG  [128 m][K1=48 pad, stride 56 bf16]  hi/lo
//   H1   [128 m][K2=64,     stride 72 bf16]  hi/lo
//   W1T  [64 n][stride 56]  hi/lo   (W1 transposed, rows 35..47 zero)
//   W2T  [64 n][stride 72]  hi/lo
// sOut (fp32, stride 66) reuses MSG+H1 region after GEMM2.
// ---------------------------------------------------------------------------
#define O_MSG_HI 0
#define O_MSG_LO 14336
#define O_H1_HI  28672
#define O_H1_LO  47104
#define O_W1_HI  65536
#define O_W1_LO  72704
#define O_W2_HI  79872
#define O_W2_LO  89088
#define O_B1     98304
#define O_B2     98560
#define O_DST    98816
#define SMEM_BYTES 99328
#define SK1 56
#define SK2 72

// ---------------------------------------------------------------------------
__device__ __forceinline__ uint32_t smem_u32(const void* p) {
    uint32_t a;
    asm("{ .reg .u64 t; cvta.to.shared.u64 t, %1; cvt.u32.u64 %0, t; }" : "=r"(a) : "l"(p));
    return a;
}
__device__ __forceinline__ void ldsm4(uint32_t* r, uint32_t addr) {
    asm volatile("ldmatrix.sync.aligned.m8n8.x4.shared.b16 {%0,%1,%2,%3}, [%4];"
        : "=r"(r[0]), "=r"(r[1]), "=r"(r[2]), "=r"(r[3]) : "r"(addr));
}
__device__ __forceinline__ void mma_bf16(float* c, const uint32_t* a, uint32_t b0, uint32_t b1) {
    asm volatile("mma.sync.aligned.m16n8k16.row.col.f32.bf16.bf16.f32 "
        "{%0,%1,%2,%3}, {%4,%5,%6,%7}, {%8,%9}, {%0,%1,%2,%3};"
        : "+f"(c[0]), "+f"(c[1]), "+f"(c[2]), "+f"(c[3])
        : "r"(a[0]), "r"(a[1]), "r"(a[2]), "r"(a[3]), "r"(b0), "r"(b1));
}
// split (a,b) into packed bf16x2 hi and lo words (v = hi + lo to ~16 bits)
__device__ __forceinline__ void split2(float a, float b, uint32_t& hi, uint32_t& lo) {
    __nv_bfloat162 h = __floats2bfloat162_rn(a, b);
    float ra = a - __bfloat162float(h.x);
    float rb = b - __bfloat162float(h.y);
    __nv_bfloat162 l = __floats2bfloat162_rn(ra, rb);
    hi = *(uint32_t*)&h; lo = *(uint32_t*)&l;
}

// ---------------------------------------------------------------------------
__global__ void k_detect(const int* __restrict__ ei_raw) {
    __shared__ int any_nonzero;
    if (threadIdx.x == 0) any_nonzero = 0;
    __syncthreads();
    int w = ei_raw[2 * threadIdx.x + 1];
    if (w != 0) atomicOr(&any_nonzero, 1);
    __syncthreads();
    if (threadIdx.x == 0) g_ei_is64 = any_nonzero ? 0 : 1;
}

__global__ void k_zero() {
    int i = blockIdx.x * blockDim.x + threadIdx.x;
    if (i < N_NODES * 64 / 4)
        ((float4*)g_agg)[i] = make_float4(0.f, 0.f, 0.f, 0.f);
}

// ---------------------------------------------------------------------------
// Fused message kernel: 128 msgs/block, 256 threads (8 warps), warp w owns
// m16-tile w across all 64 output features. bf16 3-pass error-compensated
// mma (HMMA) via ldmatrix. Then coalesced predicated atomicMax scatter.
// ---------------------------------------------------------------------------
__global__ __launch_bounds__(256, 2) void k_msg(
    const float* __restrict__ x, const float* __restrict__ pos,
    const void* __restrict__ ei_raw,
    const float* __restrict__ W1, const float* __restrict__ bias1,
    const float* __restrict__ W2, const float* __restrict__ bias2)
{
    extern __shared__ char smc[];
    const uint32_t smb = smem_u32(smc);
    uint32_t* MSG_HI = (uint32_t*)(smc + O_MSG_HI);
    uint32_t* MSG_LO = (uint32_t*)(smc + O_MSG_LO);
    uint32_t* H1_HI  = (uint32_t*)(smc + O_H1_HI);
    uint32_t* H1_LO  = (uint32_t*)(smc + O_H1_LO);
    uint32_t* W1_HI  = (uint32_t*)(smc + O_W1_HI);
    uint32_t* W1_LO  = (uint32_t*)(smc + O_W1_LO);
    uint32_t* W2_HI  = (uint32_t*)(smc + O_W2_HI);
    uint32_t* W2_LO  = (uint32_t*)(smc + O_W2_LO);
    float* sB1 = (float*)(smc + O_B1);
    float* sB2 = (float*)(smc + O_B2);
    int*   sDst = (int*)(smc + O_DST);
    float* sOut = (float*)smc;              // stride 66 floats, 33792 B

    const int tid = threadIdx.x;
    const int wid = tid >> 5;
    const int lid = tid & 31;

    // ---- stage split weights (W^T, [n][k]) ----
    for (int i = tid; i < 64 * 24; i += 256) {          // W1T: 24 words (K1=48)
        int n = i / 24, w = i % 24, k = 2 * w;
        float va = (k < 35)     ? W1[k * 64 + n]       : 0.f;
        float vb = (k + 1 < 35) ? W1[(k + 1) * 64 + n] : 0.f;
        uint32_t hi, lo; split2(va, vb, hi, lo);
        W1_HI[n * 28 + w] = hi; W1_LO[n * 28 + w] = lo;
    }
    for (int i = tid; i < 64 * 32; i += 256) {          // W2T: 32 words (K2=64)
        int n = i / 32, w = i % 32, k = 2 * w;
        uint32_t hi, lo; split2(W2[k * 64 + n], W2[(k + 1) * 64 + n], hi, lo);
        W2_HI[n * 36 + w] = hi; W2_LO[n * 36 + w] = lo;
    }
    if (tid < 64) sB1[tid] = bias1[tid];
    else if (tid < 128) sB2[tid - 64] = bias2[tid - 64];

    // ---- gather: 2 threads per message row ----
    {
        int r = tid >> 1, h = tid & 1;
        int m = blockIdx.x * TILE_E + r;
        int src = 0, dst = -1;
        if (m < E_EDGES) {
            if (g_ei_is64) { const long long* e = (const long long*)ei_raw;
                             src = (int)e[m]; dst = (int)e[E_EDGES + m]; }
            else           { const int* e = (const int*)ei_raw;
                             src = e[m]; dst = e[E_EDGES + m]; }
            if ((unsigned)src >= N_NODES) src = 0;
            if ((unsigned)dst >= N_NODES) dst = 0;
        } else if (m < M_TOTAL) { src = m - E_EDGES; dst = src; }
        if (h == 0) sDst[r] = dst;

        const float4* xp = (const float4*)(x + (size_t)src * 32 + h * 16);
        uint32_t* mh = MSG_HI + r * 28 + h * 8;
        uint32_t* ml = MSG_LO + r * 28 + h * 8;
        #pragma unroll
        for (int q = 0; q < 4; q++) {
            float4 v = __ldg(xp + q);
            uint32_t h0, l0, h1, l1;
            split2(v.x, v.y, h0, l0);
            split2(v.z, v.w, h1, l1);
            mh[2 * q] = h0; mh[2 * q + 1] = h1;
            ml[2 * q] = l0; ml[2 * q + 1] = l1;
        }
        if (h) {   // pos diffs -> k 32..34, zeros to 47 (words 16..23 of row)
            float p0 = 0.f, p1 = 0.f, p2 = 0.f;
            if (dst >= 0 && m < E_EDGES) {
                p0 = pos[src * 3 + 0] - pos[dst * 3 + 0];
                p1 = pos[src * 3 + 1] - pos[dst * 3 + 1];
                p2 = pos[src * 3 + 2] - pos[dst * 3 + 2];
            }
            uint32_t hh, ll;
            split2(p0, p1, hh, ll); mh[8] = hh; ml[8] = ll;
            split2(p2, 0.f, hh, ll); mh[9] = hh; ml[9] = ll;
            #pragma unroll
            for (int w = 10; w < 16; w++) { mh[w] = 0u; ml[w] = 0u; }
        }
    }
    __syncthreads();

    float acc[8][4];
    const int mt = wid;                       // m16-tile index (rows mt*16..+15)
    const int arow  = lid & 15;               // ldmatrix A: row within tile
    const int akoff = (lid >> 4) * 8;         //             k sub-tile
    const int bn = (lid & 7) + ((lid & 16) ? 8 : 0);  // ldmatrix B: n row
    const int bk = ((lid >> 3) & 1) * 8;              //             k sub-tile
    const int cq = lid & 3;                   // quad id (output col pair)

    // ---- GEMM1: H1 = relu(MSG @ W1T^T + b1), K1=48, 3 chunks ----
    #pragma unroll
    for (int nb = 0; nb < 8; nb++) {
        int c = 8 * nb + 2 * cq;
        acc[nb][0] = sB1[c]; acc[nb][1] = sB1[c + 1];
        acc[nb][2] = sB1[c]; acc[nb][3] = sB1[c + 1];
    }
    #pragma unroll
    for (int kc = 0; kc < 3; kc++) {
        const int k0 = kc * 16;
        uint32_t ahi[4], alo[4];
        uint32_t aaddr = smb + O_MSG_HI + (mt * 16 + arow) * (SK1 * 2) + (k0 + akoff) * 2;
        ldsm4(ahi, aaddr);
        ldsm4(alo, aaddr + (O_MSG_LO - O_MSG_HI));
        #pragma unroll
        for (int half = 0; half < 4; half++) {
            uint32_t bhi[4], blo[4];
            uint32_t baddr = smb + O_W1_HI + (half * 16 + bn) * (SK1 * 2) + (k0 + bk) * 2;
            ldsm4(bhi, baddr);
            ldsm4(blo, baddr + (O_W1_LO - O_W1_HI));
            #pragma unroll
            for (int t = 0; t < 2; t++) {
                int nb = half * 2 + t;
                mma_bf16(acc[nb], ahi, bhi[2 * t], bhi[2 * t + 1]);
                mma_bf16(acc[nb], alo, bhi[2 * t], bhi[2 * t + 1]);
                mma_bf16(acc[nb], ahi, blo[2 * t], blo[2 * t + 1]);
            }
        }
    }
    // epilogue 1: relu + split -> H1 (bank-conflict-free: word bank == lid)
    {
        int rA = mt * 16 + (lid >> 2);
        #pragma unroll
        for (int nb = 0; nb < 8; nb++) {
            int wofs = 4 * nb + cq;
            uint32_t hi, lo;
            split2(fmaxf(acc[nb][0], 0.f), fmaxf(acc[nb][1], 0.f), hi, lo);
            H1_HI[rA * 36 + wofs] = hi; H1_LO[rA * 36 + wofs] = lo;
            split2(fmaxf(acc[nb][2], 0.f), fmaxf(acc[nb][3], 0.f), hi, lo);
            H1_HI[(rA + 8) * 36 + wofs] = hi; H1_LO[(rA + 8) * 36 + wofs] = lo;
        }
    }
    __syncthreads();

    // ---- GEMM2: out = relu(H1 @ W2T^T + b2), K2=64, 4 chunks ----
    #pragma unroll
    for (int nb = 0; nb < 8; nb++) {
        int c = 8 * nb + 2 * cq;
        acc[nb][0] = sB2[c]; acc[nb][1] = sB2[c + 1];
        acc[nb][2] = sB2[c]; acc[nb][3] = sB2[c + 1];
    }
    #pragma unroll
    for (int kc = 0; kc < 4; kc++) {
        const int k0 = kc * 16;
        uint32_t ahi[4], alo[4];
        uint32_t aaddr = smb + O_H1_HI + (mt * 16 + arow) * (SK2 * 2) + (k0 + akoff) * 2;
        ldsm4(ahi, aaddr);
        ldsm4(alo, aaddr + (O_H1_LO - O_H1_HI));
        #pragma unroll
        for (int half = 0; half < 4; half++) {
            uint32_t bhi[4], blo[4];
            uint32_t baddr = smb + O_W2_HI + (half * 16 + bn) * (SK2 * 2) + (k0 + bk) * 2;
            ldsm4(bhi, baddr);
            ldsm4(blo, baddr + (O_W2_LO - O_W2_HI));
            #pragma unroll
            for (int t = 0; t < 2; t++) {
                int nb = half * 2 + t;
                mma_bf16(acc[nb], ahi, bhi[2 * t], bhi[2 * t + 1]);
                mma_bf16(acc[nb], alo, bhi[2 * t], bhi[2 * t + 1]);
                mma_bf16(acc[nb], ahi, blo[2 * t], blo[2 * t + 1]);
            }
        }
    }
    __syncthreads();   // all H1/MSG reads complete before sOut overwrites

    // epilogue 2: relu -> sOut (fp32, stride 66)
    {
        int rA = mt * 16 + (lid >> 2);
        #pragma unroll
        for (int nb = 0; nb < 8; nb++) {
            int c = 8 * nb + 2 * cq;
            float2 v0 = make_float2(fmaxf(acc[nb][0], 0.f), fmaxf(acc[nb][1], 0.f));
            float2 v1 = make_float2(fmaxf(acc[nb][2], 0.f), fmaxf(acc[nb][3], 0.f));
            *(float2*)(sOut + rA * 66 + c)       = v0;
            *(float2*)(sOut + (rA + 8) * 66 + c) = v1;
        }
    }
    __syncthreads();

    // ---- coalesced predicated max scatter: warp per message ----
    // values >= 0 (ReLU), agg zero-initialized -> signed-int max on bits OK.
    for (int m = wid; m < TILE_E; m += 8) {
        int dst = sDst[m];
        if (dst < 0) continue;
        float v0 = sOut[m * 66 + lid];
        float v1 = sOut[m * 66 + 32 + lid];
        int* ap = (int*)g_agg + (size_t)dst * 64;
        if (v0 > 0.f) atomicMax(ap + lid,      __float_as_int(v0));
        if (v1 > 0.f) atomicMax(ap + 32 + lid, __float_as_int(v1));
    }
}

// ---------------------------------------------------------------------------
// Kernel 2: out = agg @ Wg + bg    [50000,64] x [64,128]
// ---------------------------------------------------------------------------
#define SMO_A 0
#define SMO_W (64 * 68)
#define SMEM_OUT_BYTES ((64 * 68 + 64 * 128) * 4)

__global__ __launch_bounds__(128) void k_out(
    const float* __restrict__ Wg, const float* __restrict__ bg,
    float* __restrict__ out)
{
    extern __shared__ float sm[];
    float* sA = sm + SMO_A;
    float* sW = sm + SMO_W;
    const int tid = threadIdx.x;
    const int nbase = blockIdx.x * 64;

    {
        float4* dst4 = (float4*)sW;
        const float4* src4 = (const float4*)Wg;
        for (int i = tid; i < 64 * 32; i += 128) dst4[i] = __ldg(src4 + i);
    }
    for (int idx = tid; idx < 64 * 16; idx += 128) {
        int rr = idx >> 4, c4 = idx & 15;
        float4 v = make_float4(0.f, 0.f, 0.f, 0.f);
        if (nbase + rr < N_NODES)
            v = *(const float4*)(g_agg + (size_t)(nbase + rr) * 64 + c4 * 4);
        *(float4*)(sA + rr * 68 + c4 * 4) = v;
    }
    __syncthreads();

    const int tx = tid & 15;
    const int ty = tid >> 4;
    const int fbase = tx * 8;

    float acc[8][8];
    float bj[8];
    #pragma unroll
    for (int j = 0; j < 8; j++) bj[j] = __ldg(&bg[fbase + j]);
    #pragma unroll
    for (int i = 0; i < 8; i++)
        #pragma unroll
        for (int j = 0; j < 8; j++) acc[i][j] = bj[j];

    for (int k4 = 0; k4 < 16; k4++) {
        const int k0 = k4 * 4;
        float4 wv[4][2];
        #pragma unroll
        for (int kk = 0; kk < 4; kk++) {
            wv[kk][0] = *(const float4*)(sW + (k0 + kk) * 128 + fbase);
            wv[kk][1] = *(const float4*)(sW + (k0 + kk) * 128 + fbase + 4);
        }
        #pragma unroll
        for (int i = 0; i < 8; i++) {
            float4 av = *(const float4*)(sA + (ty + 8 * i) * 68 + k0);
            float a4[4] = {av.x, av.y, av.z, av.w};
            #pragma unroll
            for (int kk = 0; kk < 4; kk++) {
                const float* w = &wv[kk][0].x;
                #pragma unroll
                for (int j = 0; j < 8; j++)
                    acc[i][j] = fmaf(a4[kk], w[j], acc[i][j]);
            }
        }
    }

    #pragma unroll
    for (int i = 0; i < 8; i++) {
        int n = nbase + ty + 8 * i;
        if (n < N_NODES) {
            float4 v0, v1;
            v0.x = acc[i][0]; v0.y = acc[i][1]; v0.z = acc[i][2]; v0.w = acc[i][3];
            v1.x = acc[i][4]; v1.y = acc[i][5]; v1.z = acc[i][6]; v1.w = acc[i][7];
            *(float4*)(out + (size_t)n * 128 + fbase)     = v0;
            *(float4*)(out + (size_t)n * 128 + fbase + 4) = v1;
        }
    }
}

// ---------------------------------------------------------------------------
extern "C" void kernel_launch(void* const* d_in, const int* in_sizes, int n_in,
                              void* d_out, int out_size) {
    const float* x   = (const float*)d_in[0];
    const float* pos = (const float*)d_in[1];
    const void*  ei  = d_in[2];
    const float* W1  = (const float*)d_in[3];
    const float* b1  = (const float*)d_in[4];
    const float* W2  = (const float*)d_in[5];
    const float* b2  = (const float*)d_in[6];
    const float* Wg  = (const float*)d_in[7];
    const float* bg  = (const float*)d_in[8];
    float* out = (float*)d_out;

    cudaFuncSetAttribute(k_msg, cudaFuncAttributeMaxDynamicSharedMemorySize, SMEM_BYTES);
    cudaFuncSetAttribute(k_out, cudaFuncAttributeMaxDynamicSharedMemorySize, SMEM_OUT_BYTES);

    k_detect<<<1, 1024>>>((const int*)ei);
    k_zero<<<(N_NODES * 64 / 4 + 255) / 256, 256>>>();
    k_msg<<<NT, 256, SMEM_BYTES>>>(x, pos, ei, W1, b1, W2, b2);
    k_out<<<(N_NODES + 63) / 64, 128, SMEM_OUT_BYTES>>>(Wg, bg, out);
}

// round 9
// speedup vs baseline: 2.5391x; 1.0249x over previous
#include <cuda_runtime.h>
#include <cuda_bf16.h>
#include <cstdint>

#define N_NODES 50000
#define E_EDGES 1600000
#define M_TOTAL (E_EDGES + N_NODES)
#define TILE_E 128
#define NT ((M_TOTAL + TILE_E - 1) / TILE_E)   // 12891

__device__ float g_agg[N_NODES * 64];
__device__ float g_Y1[N_NODES * 64];           // x @ W1[:32] + b1, fp32
__device__ int g_ei_is64;

// ---------------------------------------------------------------------------
__device__ __forceinline__ uint32_t smem_u32(const void* p) {
    uint32_t a;
    asm("{ .reg .u64 t; cvta.to.shared.u64 t, %1; cvt.u32.u64 %0, t; }" : "=r"(a) : "l"(p));
    return a;
}
__device__ __forceinline__ void ldsm4(uint32_t* r, uint32_t addr) {
    asm volatile("ldmatrix.sync.aligned.m8n8.x4.shared.b16 {%0,%1,%2,%3}, [%4];"
        : "=r"(r[0]), "=r"(r[1]), "=r"(r[2]), "=r"(r[3]) : "r"(addr));
}
__device__ __forceinline__ void mma_bf16(float* c, const uint32_t* a, uint32_t b0, uint32_t b1) {
    asm volatile("mma.sync.aligned.m16n8k16.row.col.f32.bf16.bf16.f32 "
        "{%0,%1,%2,%3}, {%4,%5,%6,%7}, {%8,%9}, {%0,%1,%2,%3};"
        : "+f"(c[0]), "+f"(c[1]), "+f"(c[2]), "+f"(c[3])
        : "r"(a[0]), "r"(a[1]), "r"(a[2]), "r"(a[3]), "r"(b0), "r"(b1));
}
__device__ __forceinline__ void split2(float a, float b, uint32_t& hi, uint32_t& lo) {
    __nv_bfloat162 h = __floats2bfloat162_rn(a, b);
    float ra = a - __bfloat162float(h.x);
    float rb = b - __bfloat162float(h.y);
    __nv_bfloat162 l = __floats2bfloat162_rn(ra, rb);
    hi = *(uint32_t*)&h; lo = *(uint32_t*)&l;
}

// ---------------------------------------------------------------------------
__global__ void k_detect(const int* __restrict__ ei_raw) {
    __shared__ int any_nonzero;
    if (threadIdx.x == 0) any_nonzero = 0;
    __syncthreads();
    int w = ei_raw[2 * threadIdx.x + 1];
    if (w != 0) atomicOr(&any_nonzero, 1);
    __syncthreads();
    if (threadIdx.x == 0) g_ei_is64 = any_nonzero ? 0 : 1;
}

__global__ void k_zero() {
    int i = blockIdx.x * blockDim.x + threadIdx.x;
    if (i < N_NODES * 64 / 4)
        ((float4*)g_agg)[i] = make_float4(0.f, 0.f, 0.f, 0.f);
}

// ---------------------------------------------------------------------------
// k_pre: Y1 = x @ W1[:32,:] + b1   [50000,32] @ [32,64] (fp32 exact)
// ---------------------------------------------------------------------------
#define SPX 0                          // 64*36 floats
#define SPW (64 * 36)                  // 32*64 floats
#define SMEM_PRE_BYTES ((64 * 36 + 32 * 64) * 4)

__global__ __launch_bounds__(128) void k_pre(
    const float* __restrict__ x, const float* __restrict__ W1,
    const float* __restrict__ b1)
{
    extern __shared__ float sm[];
    float* sX = sm + SPX;
    float* sW = sm + SPW;
    const int tid = threadIdx.x;
    const int nbase = blockIdx.x * 64;

    for (int i = tid; i < 32 * 16; i += 128)          // W1[:32] as float4
        ((float4*)sW)[i] = __ldg((const float4*)W1 + i);
    for (int idx = tid; idx < 64 * 8; idx += 128) {   // x tile, stride 36
        int r = idx >> 3, c4 = idx & 7;
        float4 v = make_float4(0.f, 0.f, 0.f, 0.f);
        if (nbase + r < N_NODES)
            v = *(const float4*)(x + (size_t)(nbase + r) * 32 + c4 * 4);
        *(float4*)(sX + r * 36 + c4 * 4) = v;
    }
    __syncthreads();

    const int tx = tid & 7, ty = tid >> 3;
    const int fbase = tx * 8;
    float acc[4][8];
    float bj[8];
    #pragma unroll
    for (int j = 0; j < 8; j++) bj[j] = __ldg(&b1[fbase + j]);
    #pragma unroll
    for (int i = 0; i < 4; i++)
        #pragma unroll
        for (int j = 0; j < 8; j++) acc[i][j] = bj[j];

    for (int k4 = 0; k4 < 8; k4++) {
        const int k0 = k4 * 4;
        float4 wv[4][2];
        #pragma unroll
        for (int kk = 0; kk < 4; kk++) {
            wv[kk][0] = *(const float4*)(sW + (k0 + kk) * 64 + fbase);
            wv[kk][1] = *(const float4*)(sW + (k0 + kk) * 64 + fbase + 4);
        }
        #pragma unroll
        for (int i = 0; i < 4; i++) {
            float4 av = *(const float4*)(sX + (ty + 16 * i) * 36 + k0);
            float a4[4] = {av.x, av.y, av.z, av.w};
            #pragma unroll
            for (int kk = 0; kk < 4; kk++) {
                const float* w = &wv[kk][0].x;
                #pragma unroll
                for (int j = 0; j < 8; j++)
                    acc[i][j] = fmaf(a4[kk], w[j], acc[i][j]);
            }
        }
    }
    #pragma unroll
    for (int i = 0; i < 4; i++) {
        int n = nbase + ty + 16 * i;
        if (n < N_NODES) {
            float4 v0, v1;
            v0.x = acc[i][0]; v0.y = acc[i][1]; v0.z = acc[i][2]; v0.w = acc[i][3];
            v1.x = acc[i][4]; v1.y = acc[i][5]; v1.z = acc[i][6]; v1.w = acc[i][7];
            *(float4*)(g_Y1 + (size_t)n * 64 + fbase)     = v0;
            *(float4*)(g_Y1 + (size_t)n * 64 + fbase + 4) = v1;
        }
    }
}

// ---------------------------------------------------------------------------
// k_msg: gather Y1[src] + fp32 pos-tail + relu -> split H1 -> bf16 3-pass
// GEMM2 (H1 @ W2^T + b2) -> relu -> coalesced predicated atomicMax.
// ---------------------------------------------------------------------------
#define O_H1_HI  0                      // 128 x 36 words (stride 72 bf16)
#define O_H1_LO  18432
#define O_W2_HI  36864                  // 64 x 36 words
#define O_W2_LO  46080
#define O_B2     55296                  // 64 fp32
#define O_WT     55552                  // 3 x 64 fp32 (W1 rows 32..34)
#define O_DST    56320                  // 128 ints
#define SMEM_MSG_BYTES 56832
#define SK2 72

__global__ __launch_bounds__(256, 2) void k_msg(
    const float* __restrict__ pos,
    const void* __restrict__ ei_raw,
    const float* __restrict__ W1,
    const float* __restrict__ W2, const float* __restrict__ bias2)
{
    extern __shared__ char smc[];
    const uint32_t smb = smem_u32(smc);
    uint32_t* H1_HI = (uint32_t*)(smc + O_H1_HI);
    uint32_t* H1_LO = (uint32_t*)(smc + O_H1_LO);
    uint32_t* W2_HI = (uint32_t*)(smc + O_W2_HI);
    uint32_t* W2_LO = (uint32_t*)(smc + O_W2_LO);
    float* sB2 = (float*)(smc + O_B2);
    float* sWT = (float*)(smc + O_WT);
    int*   sDst = (int*)(smc + O_DST);
    float* sOut = (float*)smc;          // stride 66 fp32, reuses H1 region

    const int tid = threadIdx.x;
    const int wid = tid >> 5;
    const int lid = tid & 31;

    // ---- stage W2^T split, b2, W1 pos-rows ----
    for (int i = tid; i < 64 * 32; i += 256) {
        int n = i / 32, w = i % 32, k = 2 * w;
        uint32_t hi, lo; split2(W2[k * 64 + n], W2[(k + 1) * 64 + n], hi, lo);
        W2_HI[n * 36 + w] = hi; W2_LO[n * 36 + w] = lo;
    }
    if (tid < 64) sB2[tid] = bias2[tid];
    else if (tid >= 64 && tid < 256) {
        int i = tid - 64;
        if (i < 192) sWT[i] = W1[(32 + i / 64) * 64 + (i % 64)];
    }
    __syncthreads();   // *** gather below READS sWT — must wait for staging ***

    // ---- gather + exact layer-1 epilogue: 2 threads per message row ----
    {
        int r = tid >> 1, h = tid & 1;
        int m = blockIdx.x * TILE_E + r;
        int src = 0, dst = -1;
        if (m < E_EDGES) {
            if (g_ei_is64) { const long long* e = (const long long*)ei_raw;
                             src = (int)e[m]; dst = (int)e[E_EDGES + m]; }
            else           { const int* e = (const int*)ei_raw;
                             src = e[m]; dst = e[E_EDGES + m]; }
            if ((unsigned)src >= N_NODES) src = 0;
            if ((unsigned)dst >= N_NODES) dst = 0;
        } else if (m < M_TOTAL) { src = m - E_EDGES; dst = src; }
        if (h == 0) sDst[r] = dst;

        float p0 = 0.f, p1 = 0.f, p2 = 0.f;
        if (dst >= 0 && m < E_EDGES) {
            p0 = pos[src * 3 + 0] - pos[dst * 3 + 0];
            p1 = pos[src * 3 + 1] - pos[dst * 3 + 1];
            p2 = pos[src * 3 + 2] - pos[dst * 3 + 2];
        }

        const float4* yp = (const float4*)(g_Y1 + (size_t)src * 64 + h * 32);
        uint32_t* hh = H1_HI + r * 36 + h * 16;
        uint32_t* ll = H1_LO + r * 36 + h * 16;
        #pragma unroll
        for (int q = 0; q < 8; q++) {
            float4 y = __ldg(yp + q);
            int n0 = h * 32 + q * 4;
            float4 w0 = *(const float4*)(sWT + n0);
            float4 w1 = *(const float4*)(sWT + 64 + n0);
            float4 w2 = *(const float4*)(sWT + 128 + n0);
            float v0 = fmaxf(fmaf(p0, w0.x, fmaf(p1, w1.x, fmaf(p2, w2.x, y.x))), 0.f);
            float v1 = fmaxf(fmaf(p0, w0.y, fmaf(p1, w1.y, fmaf(p2, w2.y, y.y))), 0.f);
            float v2 = fmaxf(fmaf(p0, w0.z, fmaf(p1, w1.z, fmaf(p2, w2.z, y.z))), 0.f);
            float v3 = fmaxf(fmaf(p0, w0.w, fmaf(p1, w1.w, fmaf(p2, w2.w, y.w))), 0.f);
            uint32_t a, b;
            split2(v0, v1, a, b); hh[2 * q] = a;     ll[2 * q] = b;
            split2(v2, v3, a, b); hh[2 * q + 1] = a; ll[2 * q + 1] = b;
        }
    }
    __syncthreads();

    // ---- GEMM2: out = relu(H1 @ W2^T + b2), K=64, bf16 3-pass ----
    float acc[8][4];
    const int mt = wid;
    const int arow  = lid & 15;
    const int akoff = (lid >> 4) * 8;
    const int bn = (lid & 7) + ((lid & 16) ? 8 : 0);
    const int bk = ((lid >> 3) & 1) * 8;
    const int cq = lid & 3;

    #pragma unroll
    for (int nb = 0; nb < 8; nb++) {
        int c = 8 * nb + 2 * cq;
        acc[nb][0] = sB2[c]; acc[nb][1] = sB2[c + 1];
        acc[nb][2] = sB2[c]; acc[nb][3] = sB2[c + 1];
    }
    #pragma unroll
    for (int kc = 0; kc < 4; kc++) {
        const int k0 = kc * 16;
        uint32_t ahi[4], alo[4];
        uint32_t aaddr = smb + O_H1_HI + (mt * 16 + arow) * (SK2 * 2) + (k0 + akoff) * 2;
        ldsm4(ahi, aaddr);
        ldsm4(alo, aaddr + (O_H1_LO - O_H1_HI));
        #pragma unroll
        for (int half = 0; half < 4; half++) {
            uint32_t bhi[4], blo[4];
            uint32_t baddr = smb + O_W2_HI + (half * 16 + bn) * (SK2 * 2) + (k0 + bk) * 2;
            ldsm4(bhi, baddr);
            ldsm4(blo, baddr + (O_W2_LO - O_W2_HI));
            int n0 = half * 2, n1 = half * 2 + 1;
            mma_bf16(acc[n0], ahi, bhi[0], bhi[1]);
            mma_bf16(acc[n1], ahi, bhi[2], bhi[3]);
            mma_bf16(acc[n0], alo, bhi[0], bhi[1]);
            mma_bf16(acc[n1], alo, bhi[2], bhi[3]);
            mma_bf16(acc[n0], ahi, blo[0], blo[1]);
            mma_bf16(acc[n1], ahi, blo[2], blo[3]);
        }
    }
    __syncthreads();   // all H1 reads complete before sOut overwrites

    // epilogue: relu -> sOut (fp32, stride 66)
    {
        int rA = mt * 16 + (lid >> 2);
        #pragma unroll
        for (int nb = 0; nb < 8; nb++) {
            int c = 8 * nb + 2 * cq;
            float2 v0 = make_float2(fmaxf(acc[nb][0], 0.f), fmaxf(acc[nb][1], 0.f));
            float2 v1 = make_float2(fmaxf(acc[nb][2], 0.f), fmaxf(acc[nb][3], 0.f));
            *(float2*)(sOut + rA * 66 + c)       = v0;
            *(float2*)(sOut + (rA + 8) * 66 + c) = v1;
        }
    }
    __syncthreads();

    // coalesced predicated max scatter (values >= 0, agg zero-initialized)
    for (int m = wid; m < TILE_E; m += 8) {
        int dst = sDst[m];
        if (dst < 0) continue;
        float v0 = sOut[m * 66 + lid];
        float v1 = sOut[m * 66 + 32 + lid];
        int* ap = (int*)g_agg + (size_t)dst * 64;
        if (v0 > 0.f) atomicMax(ap + lid,      __float_as_int(v0));
        if (v1 > 0.f) atomicMax(ap + 32 + lid, __float_as_int(v1));
    }
}

// ---------------------------------------------------------------------------
// k_out: out = agg @ Wg + bg    [50000,64] x [64,128]
// ---------------------------------------------------------------------------
#define SMO_A 0
#define SMO_W (64 * 68)
#define SMEM_OUT_BYTES ((64 * 68 + 64 * 128) * 4)

__global__ __launch_bounds__(128) void k_out(
    const float* __restrict__ Wg, const float* __restrict__ bg,
    float* __restrict__ out)
{
    extern __shared__ float sm[];
    float* sA = sm + SMO_A;
    float* sW = sm + SMO_W;
    const int tid = threadIdx.x;
    const int nbase = blockIdx.x * 64;

    {
        float4* dst4 = (float4*)sW;
        const float4* src4 = (const float4*)Wg;
        for (int i = tid; i < 64 * 32; i += 128) dst4[i] = __ldg(src4 + i);
    }
    for (int idx = tid; idx < 64 * 16; idx += 128) {
        int rr = idx >> 4, c4 = idx & 15;
        float4 v = make_float4(0.f, 0.f, 0.f, 0.f);
        if (nbase + rr < N_NODES)
            v = *(const float4*)(g_agg + (size_t)(nbase + rr) * 64 + c4 * 4);
        *(float4*)(sA + rr * 68 + c4 * 4) = v;
    }
    __syncthreads();

    const int tx = tid & 15;
    const int ty = tid >> 4;
    const int fbase = tx * 8;

    float acc[8][8];
    float bj[8];
    #pragma unroll
    for (int j = 0; j < 8; j++) bj[j] = __ldg(&bg[fbase + j]);
    #pragma unroll
    for (int i = 0; i < 8; i++)
        #pragma unroll
        for (int j = 0; j < 8; j++) acc[i][j] = bj[j];

    for (int k4 = 0; k4 < 16; k4++) {
        const int k0 = k4 * 4;
        float4 wv[4][2];
        #pragma unroll
        for (int kk = 0; kk < 4; kk++) {
            wv[kk][0] = *(const float4*)(sW + (k0 + kk) * 128 + fbase);
            wv[kk][1] = *(const float4*)(sW + (k0 + kk) * 128 + fbase + 4);
        }
        #pragma unroll
        for (int i = 0; i < 8; i++) {
            float4 av = *(const float4*)(sA + (ty + 8 * i) * 68 + k0);
            float a4[4] = {av.x, av.y, av.z, av.w};
            #pragma unroll
            for (int kk = 0; kk < 4; kk++) {
                const float* w = &wv[kk][0].x;
                #pragma unroll
                for (int j = 0; j < 8; j++)
                    acc[i][j] = fmaf(a4[kk], w[j], acc[i][j]);
            }
        }
    }

    #pragma unroll
    for (int i = 0; i < 8; i++) {
        int n = nbase + ty + 8 * i;
        if (n < N_NODES) {
            float4 v0, v1;
            v0.x = acc[i][0]; v0.y = acc[i][1]; v0.z = acc[i][2]; v0.w = acc[i][3];
            v1.x = acc[i][4]; v1.y = acc[i][5]; v1.z = acc[i][6]; v1.w = acc[i][7];
            *(float4*)(out + (size_t)n * 128 + fbase)     = v0;
            *(float4*)(out + (size_t)n * 128 + fbase + 4) = v1;
        }
    }
}

// ---------------------------------------------------------------------------
extern "C" void kernel_launch(void* const* d_in, const int* in_sizes, int n_in,
                              void* d_out, int out_size) {
    const float* x   = (const float*)d_in[0];
    const float* pos = (const float*)d_in[1];
    const void*  ei  = d_in[2];
    const float* W1  = (const float*)d_in[3];
    const float* b1  = (const float*)d_in[4];
    const float* W2  = (const float*)d_in[5];
    const float* b2  = (const float*)d_in[6];
    const float* Wg  = (const float*)d_in[7];
    const float* bg  = (const float*)d_in[8];
    float* out = (float*)d_out;

    cudaFuncSetAttribute(k_msg, cudaFuncAttributeMaxDynamicSharedMemorySize, SMEM_MSG_BYTES);
    cudaFuncSetAttribute(k_out, cudaFuncAttributeMaxDynamicSharedMemorySize, SMEM_OUT_BYTES);
    cudaFuncSetAttribute(k_pre, cudaFuncAttributeMaxDynamicSharedMemorySize, SMEM_PRE_BYTES);

    k_detect<<<1, 1024>>>((const int*)ei);
    k_zero<<<(N_NODES * 64 / 4 + 255) / 256, 256>>>();
    k_pre<<<(N_NODES + 63) / 64, 128, SMEM_PRE_BYTES>>>(x, W1, b1);
    k_msg<<<NT, 256, SMEM_MSG_BYTES>>>(pos, ei, W1, W2, b2);
    k_out<<<(N_NODES + 63) / 64, 128, SMEM_OUT_BYTES>>>(Wg, bg, out);
}

// round 10
// speedup vs baseline: 4.3443x; 1.7110x over previous
#include <cuda_runtime.h>
#include <cuda_bf16.h>
#include <cstdint>

#define N_NODES 50000
#define E_EDGES 1600000
#define M_TOTAL (E_EDGES + N_NODES)
#define TILE_E 128
#define NT ((M_TOTAL + TILE_E - 1) / TILE_E)   // 12891
#define GRID_MSG 296

__device__ float g_agg[N_NODES * 64];
__device__ float g_YS[N_NODES * 64];   // x@W1[:32] + b1 + pos@W1[32:35]
__device__ float g_P[N_NODES * 64];    // pos@W1[32:35]
__device__ int g_ei_is64;
__device__ int g_tile;

// ---------------------------------------------------------------------------
__device__ __forceinline__ uint32_t smem_u32(const void* p) {
    uint32_t a;
    asm("{ .reg .u64 t; cvta.to.shared.u64 t, %1; cvt.u32.u64 %0, t; }" : "=r"(a) : "l"(p));
    return a;
}
__device__ __forceinline__ void ldsm4(uint32_t* r, uint32_t addr) {
    asm volatile("ldmatrix.sync.aligned.m8n8.x4.shared.b16 {%0,%1,%2,%3}, [%4];"
        : "=r"(r[0]), "=r"(r[1]), "=r"(r[2]), "=r"(r[3]) : "r"(addr));
}
__device__ __forceinline__ void mma_bf16(float* c, const uint32_t* a, uint32_t b0, uint32_t b1) {
    asm volatile("mma.sync.aligned.m16n8k16.row.col.f32.bf16.bf16.f32 "
        "{%0,%1,%2,%3}, {%4,%5,%6,%7}, {%8,%9}, {%0,%1,%2,%3};"
        : "+f"(c[0]), "+f"(c[1]), "+f"(c[2]), "+f"(c[3])
        : "r"(a[0]), "r"(a[1]), "r"(a[2]), "r"(a[3]), "r"(b0), "r"(b1));
}
__device__ __forceinline__ void split2(float a, float b, uint32_t& hi, uint32_t& lo) {
    __nv_bfloat162 h = __floats2bfloat162_rn(a, b);
    float ra = a - __bfloat162float(h.x);
    float rb = b - __bfloat162float(h.y);
    __nv_bfloat162 l = __floats2bfloat162_rn(ra, rb);
    hi = *(uint32_t*)&h; lo = *(uint32_t*)&l;
}

// ---------------------------------------------------------------------------
__global__ void k_detect(const int* __restrict__ ei_raw) {
    __shared__ int any_nonzero;
    if (threadIdx.x == 0) any_nonzero = 0;
    __syncthreads();
    int w = ei_raw[2 * threadIdx.x + 1];
    if (w != 0) atomicOr(&any_nonzero, 1);
    __syncthreads();
    if (threadIdx.x == 0) g_ei_is64 = any_nonzero ? 0 : 1;
}

__global__ void k_zero() {
    int i = blockIdx.x * blockDim.x + threadIdx.x;
    if (i == 0) g_tile = 0;
    if (i < N_NODES * 64 / 4)
        ((float4*)g_agg)[i] = make_float4(0.f, 0.f, 0.f, 0.f);
}

// ---------------------------------------------------------------------------
// k_pre: per node, fp32-exact:
//   Y1 = x @ W1[:32] + b1 ; P = pos @ W1[32:35] ; YS = Y1 + P
// ---------------------------------------------------------------------------
#define SPX 0                          // 64*36 floats
#define SPW (64 * 36)                  // 32*64 floats
#define SPT (SPW + 32 * 64)            // 3*64 floats (W1 rows 32..34)
#define SMEM_PRE_BYTES ((SPT + 192) * 4)

__global__ __launch_bounds__(128) void k_pre(
    const float* __restrict__ x, const float* __restrict__ pos,
    const float* __restrict__ W1, const float* __restrict__ b1)
{
    extern __shared__ float sm[];
    float* sX = sm + SPX;
    float* sW = sm + SPW;
    float* sWT = sm + SPT;
    const int tid = threadIdx.x;
    const int nbase = blockIdx.x * 64;

    for (int i = tid; i < 32 * 16; i += 128)
        ((float4*)sW)[i] = __ldg((const float4*)W1 + i);
    if (tid < 64) {
        sWT[tid]       = W1[32 * 64 + tid];
        sWT[64 + tid]  = W1[33 * 64 + tid];
        sWT[128 + tid] = W1[34 * 64 + tid];
    }
    for (int idx = tid; idx < 64 * 8; idx += 128) {
        int r = idx >> 3, c4 = idx & 7;
        float4 v = make_float4(0.f, 0.f, 0.f, 0.f);
        if (nbase + r < N_NODES)
            v = *(const float4*)(x + (size_t)(nbase + r) * 32 + c4 * 4);
        *(float4*)(sX + r * 36 + c4 * 4) = v;
    }
    __syncthreads();

    const int tx = tid & 7, ty = tid >> 3;
    const int fbase = tx * 8;
    float acc[4][8];
    float bj[8];
    #pragma unroll
    for (int j = 0; j < 8; j++) bj[j] = __ldg(&b1[fbase + j]);
    #pragma unroll
    for (int i = 0; i < 4; i++)
        #pragma unroll
        for (int j = 0; j < 8; j++) acc[i][j] = bj[j];

    for (int k4 = 0; k4 < 8; k4++) {
        const int k0 = k4 * 4;
        float4 wv[4][2];
        #pragma unroll
        for (int kk = 0; kk < 4; kk++) {
            wv[kk][0] = *(const float4*)(sW + (k0 + kk) * 64 + fbase);
            wv[kk][1] = *(const float4*)(sW + (k0 + kk) * 64 + fbase + 4);
        }
        #pragma unroll
        for (int i = 0; i < 4; i++) {
            float4 av = *(const float4*)(sX + (ty + 16 * i) * 36 + k0);
            float a4[4] = {av.x, av.y, av.z, av.w};
            #pragma unroll
            for (int kk = 0; kk < 4; kk++) {
                const float* w = &wv[kk][0].x;
                #pragma unroll
                for (int j = 0; j < 8; j++)
                    acc[i][j] = fmaf(a4[kk], w[j], acc[i][j]);
            }
        }
    }
    #pragma unroll
    for (int i = 0; i < 4; i++) {
        int n = nbase + ty + 16 * i;
        if (n < N_NODES) {
            float p0 = pos[n * 3 + 0], p1 = pos[n * 3 + 1], p2 = pos[n * 3 + 2];
            float pv[8], ys[8];
            #pragma unroll
            for (int j = 0; j < 8; j++) {
                int c = fbase + j;
                pv[j] = fmaf(p0, sWT[c], fmaf(p1, sWT[64 + c], p2 * sWT[128 + c]));
                ys[j] = acc[i][j] + pv[j];
            }
            *(float4*)(g_YS + (size_t)n * 64 + fbase)     = make_float4(ys[0], ys[1], ys[2], ys[3]);
            *(float4*)(g_YS + (size_t)n * 64 + fbase + 4) = make_float4(ys[4], ys[5], ys[6], ys[7]);
            *(float4*)(g_P  + (size_t)n * 64 + fbase)     = make_float4(pv[0], pv[1], pv[2], pv[3]);
            *(float4*)(g_P  + (size_t)n * 64 + fbase + 4) = make_float4(pv[4], pv[5], pv[6], pv[7]);
        }
    }
}

// ---------------------------------------------------------------------------
// k_msg (persistent, work-stealing): per tile of 128 messages:
//   phase A: edge indices -> smem
//   phase B: coalesced gather  relu(YS[src] - P[dst])  -> split -> H1
//   GEMM2 (bf16 3-pass) -> relu -> sOut -> coalesced predicated atomicMax
// ---------------------------------------------------------------------------
#define O_H1_HI  0                      // 128 x 36 words (stride 72 bf16)
#define O_H1_LO  18432
#define O_W2_HI  36864                  // 64 x 36 words
#define O_W2_LO  46080
#define O_B2     55296                  // 64 fp32
#define O_SRC    55552                  // 128 ints
#define O_DST    56064                  // 128 ints
#define O_TI     56576
#define SMEM_MSG_BYTES 56592
#define SK2 72

__global__ __launch_bounds__(256, 2) void k_msg(
    const void* __restrict__ ei_raw,
    const float* __restrict__ W2, const float* __restrict__ bias2)
{
    extern __shared__ char smc[];
    const uint32_t smb = smem_u32(smc);
    uint32_t* H1_HI = (uint32_t*)(smc + O_H1_HI);
    uint32_t* H1_LO = (uint32_t*)(smc + O_H1_LO);
    uint32_t* W2_HI = (uint32_t*)(smc + O_W2_HI);
    uint32_t* W2_LO = (uint32_t*)(smc + O_W2_LO);
    float* sB2 = (float*)(smc + O_B2);
    int*   sSrc = (int*)(smc + O_SRC);
    int*   sDst = (int*)(smc + O_DST);
    volatile int* sTi = (volatile int*)(smc + O_TI);
    float* sOut = (float*)smc;          // stride 66 fp32, reuses H1 region

    const int tid = threadIdx.x;
    const int wid = tid >> 5;
    const int lid = tid & 31;

    // ---- stage W2^T split + b2 (once per CTA, amortized over ~43 tiles) ----
    for (int i = tid; i < 64 * 32; i += 256) {
        int n = i / 32, w = i % 32, k = 2 * w;
        uint32_t hi, lo; split2(W2[k * 64 + n], W2[(k + 1) * 64 + n], hi, lo);
        W2_HI[n * 36 + w] = hi; W2_LO[n * 36 + w] = lo;
    }
    if (tid < 64) sB2[tid] = bias2[tid];
    const int is64 = g_ei_is64;

    // mma lane mapping
    const int mt = wid;
    const int arow  = lid & 15;
    const int akoff = (lid >> 4) * 8;
    const int bnrow = (lid & 7) + ((lid & 16) ? 8 : 0);
    const int bk = ((lid >> 3) & 1) * 8;
    const int cq = lid & 3;
    // phase-B lane mapping: instr covers 2 msgs x 2 half-rows
    const int gb_m  = lid >> 4;          // msg within pair
    const int gb_h  = (lid >> 3) & 1;    // half-row
    const int gb_s  = lid & 7;           // 16B segment

    __syncthreads();

    for (;;) {
        if (tid == 0) *sTi = atomicAdd(&g_tile, 1);
        __syncthreads();   // broadcasts sTi; orders prev-iter atomics before H1 reuse
        const int t = *sTi;
        if (t >= NT) break;

        // ---- phase A: edge indices (coalesced) ----
        if (tid < TILE_E) {
            int m = t * TILE_E + tid;
            int src = 0, dst = -1;
            if (m < E_EDGES) {
                if (is64) { const long long* e = (const long long*)ei_raw;
                            src = (int)e[m]; dst = (int)e[E_EDGES + m]; }
                else      { const int* e = (const int*)ei_raw;
                            src = e[m]; dst = e[E_EDGES + m]; }
                if ((unsigned)src >= N_NODES) src = 0;
                if ((unsigned)dst >= N_NODES) dst = 0;
            } else if (m < M_TOTAL) { src = m - E_EDGES; dst = src; }
            sSrc[tid] = src; sDst[tid] = dst;
        }
        __syncthreads();

        // ---- phase B: coalesced gather, relu(YS[src]-P[dst]), split -> H1 ----
        #pragma unroll
        for (int it = 0; it < 8; it++) {
            int m = wid * 16 + it * 2 + gb_m;
            int src = sSrc[m];
            int dst = sDst[m]; if (dst < 0) dst = 0;
            int n0 = gb_h * 32 + gb_s * 4;
            float4 ys = __ldg((const float4*)(g_YS + (size_t)src * 64 + n0));
            float4 pp = __ldg((const float4*)(g_P  + (size_t)dst * 64 + n0));
            float v0 = fmaxf(ys.x - pp.x, 0.f);
            float v1 = fmaxf(ys.y - pp.y, 0.f);
            float v2 = fmaxf(ys.z - pp.z, 0.f);
            float v3 = fmaxf(ys.w - pp.w, 0.f);
            uint32_t a, b, c, d;
            split2(v0, v1, a, b);
            split2(v2, v3, c, d);
            int wofs = m * 36 + gb_h * 16 + gb_s * 2;
            *(uint2*)(H1_HI + wofs) = make_uint2(a, c);
            *(uint2*)(H1_LO + wofs) = make_uint2(b, d);
        }
        __syncthreads();

        // ---- GEMM2: out = relu(H1 @ W2^T + b2), K=64, bf16 3-pass ----
        float acc[8][4];
        #pragma unroll
        for (int nb = 0; nb < 8; nb++) {
            int c = 8 * nb + 2 * cq;
            acc[nb][0] = sB2[c]; acc[nb][1] = sB2[c + 1];
            acc[nb][2] = sB2[c]; acc[nb][3] = sB2[c + 1];
        }
        #pragma unroll
        for (int kc = 0; kc < 4; kc++) {
            const int k0 = kc * 16;
            uint32_t ahi[4], alo[4];
            uint32_t aaddr = smb + O_H1_HI + (mt * 16 + arow) * (SK2 * 2) + (k0 + akoff) * 2;
            ldsm4(ahi, aaddr);
            ldsm4(alo, aaddr + (O_H1_LO - O_H1_HI));
            #pragma unroll
            for (int half = 0; half < 4; half++) {
                uint32_t bhi[4], blo[4];
                uint32_t baddr = smb + O_W2_HI + (half * 16 + bnrow) * (SK2 * 2) + (k0 + bk) * 2;
                ldsm4(bhi, baddr);
                ldsm4(blo, baddr + (O_W2_LO - O_W2_HI));
                int n0 = half * 2, n1 = half * 2 + 1;
                mma_bf16(acc[n0], ahi, bhi[0], bhi[1]);
                mma_bf16(acc[n1], ahi, bhi[2], bhi[3]);
                mma_bf16(acc[n0], alo, bhi[0], bhi[1]);
                mma_bf16(acc[n1], alo, bhi[2], bhi[3]);
                mma_bf16(acc[n0], ahi, blo[0], blo[1]);
                mma_bf16(acc[n1], ahi, blo[2], blo[3]);
            }
        }
        __syncthreads();   // all H1 reads complete before sOut overwrites

        // epilogue: relu -> sOut (fp32, stride 66)
        {
            int rA = mt * 16 + (lid >> 2);
            #pragma unroll
            for (int nb = 0; nb < 8; nb++) {
                int c = 8 * nb + 2 * cq;
                float2 v0 = make_float2(fmaxf(acc[nb][0], 0.f), fmaxf(acc[nb][1], 0.f));
                float2 v1 = make_float2(fmaxf(acc[nb][2], 0.f), fmaxf(acc[nb][3], 0.f));
                *(float2*)(sOut + rA * 66 + c)       = v0;
                *(float2*)(sOut + (rA + 8) * 66 + c) = v1;
            }
        }
        __syncthreads();

        // coalesced predicated max scatter (values >= 0, agg zero-initialized)
        for (int m = wid; m < TILE_E; m += 8) {
            int dst = sDst[m];
            if (dst < 0) continue;
            float v0 = sOut[m * 66 + lid];
            float v1 = sOut[m * 66 + 32 + lid];
            int* ap = (int*)g_agg + (size_t)dst * 64;
            if (v0 > 0.f) atomicMax(ap + lid,      __float_as_int(v0));
            if (v1 > 0.f) atomicMax(ap + 32 + lid, __float_as_int(v1));
        }
    }
}

// ---------------------------------------------------------------------------
// k_out: out = agg @ Wg + bg    [50000,64] x [64,128]
// ---------------------------------------------------------------------------
#define SMO_A 0
#define SMO_W (64 * 68)
#define SMEM_OUT_BYTES ((64 * 68 + 64 * 128) * 4)

__global__ __launch_bounds__(128) void k_out(
    const float* __restrict__ Wg, const float* __restrict__ bg,
    float* __restrict__ out)
{
    extern __shared__ float sm[];
    float* sA = sm + SMO_A;
    float* sW = sm + SMO_W;
    const int tid = threadIdx.x;
    const int nbase = blockIdx.x * 64;

    {
        float4* dst4 = (float4*)sW;
        const float4* src4 = (const float4*)Wg;
        for (int i = tid; i < 64 * 32; i += 128) dst4[i] = __ldg(src4 + i);
    }
    for (int idx = tid; idx < 64 * 16; idx += 128) {
        int rr = idx >> 4, c4 = idx & 15;
        float4 v = make_float4(0.f, 0.f, 0.f, 0.f);
        if (nbase + rr < N_NODES)
            v = *(const float4*)(g_agg + (size_t)(nbase + rr) * 64 + c4 * 4);
        *(float4*)(sA + rr * 68 + c4 * 4) = v;
    }
    __syncthreads();

    const int tx = tid & 15;
    const int ty = tid >> 4;
    const int fbase = tx * 8;

    float acc[8][8];
    float bj[8];
    #pragma unroll
    for (int j = 0; j < 8; j++) bj[j] = __ldg(&bg[fbase + j]);
    #pragma unroll
    for (int i = 0; i < 8; i++)
        #pragma unroll
        for (int j = 0; j < 8; j++) acc[i][j] = bj[j];

    for (int k4 = 0; k4 < 16; k4++) {
        const int k0 = k4 * 4;
        float4 wv[4][2];
        #pragma unroll
        for (int kk = 0; kk < 4; kk++) {
            wv[kk][0] = *(const float4*)(sW + (k0 + kk) * 128 + fbase);
            wv[kk][1] = *(const float4*)(sW + (k0 + kk) * 128 + fbase + 4);
        }
        #pragma unroll
        for (int i = 0; i < 8; i++) {
            float4 av = *(const float4*)(sA + (ty + 8 * i) * 68 + k0);
            float a4[4] = {av.x, av.y, av.z, av.w};
            #pragma unroll
            for (int kk = 0; kk < 4; kk++) {
                const float* w = &wv[kk][0].x;
                #pragma unroll
                for (int j = 0; j < 8; j++)
                    acc[i][j] = fmaf(a4[kk], w[j], acc[i][j]);
            }
        }
    }

    #pragma unroll
    for (int i = 0; i < 8; i++) {
        int n = nbase + ty + 8 * i;
        if (n < N_NODES) {
            float4 v0, v1;
            v0.x = acc[i][0]; v0.y = acc[i][1]; v0.z = acc[i][2]; v0.w = acc[i][3];
            v1.x = acc[i][4]; v1.y = acc[i][5]; v1.z = acc[i][6]; v1.w = acc[i][7];
            *(float4*)(out + (size_t)n * 128 + fbase)     = v0;
            *(float4*)(out + (size_t)n * 128 + fbase + 4) = v1;
        }
    }
}

// ---------------------------------------------------------------------------
extern "C" void kernel_launch(void* const* d_in, const int* in_sizes, int n_in,
                              void* d_out, int out_size) {
    const float* x   = (const float*)d_in[0];
    const float* pos = (const float*)d_in[1];
    const void*  ei  = d_in[2];
    const float* W1  = (const float*)d_in[3];
    const float* b1  = (const float*)d_in[4];
    const float* W2  = (const float*)d_in[5];
    const float* b2  = (const float*)d_in[6];
    const float* Wg  = (const float*)d_in[7];
    const float* bg  = (const float*)d_in[8];
    float* out = (float*)d_out;

    cudaFuncSetAttribute(k_msg, cudaFuncAttributeMaxDynamicSharedMemorySize, SMEM_MSG_BYTES);
    cudaFuncSetAttribute(k_out, cudaFuncAttributeMaxDynamicSharedMemorySize, SMEM_OUT_BYTES);
    cudaFuncSetAttribute(k_pre, cudaFuncAttributeMaxDynamicSharedMemorySize, SMEM_PRE_BYTES);

    k_detect<<<1, 1024>>>((const int*)ei);
    k_zero<<<(N_NODES * 64 / 4 + 255) / 256, 256>>>();
    k_pre<<<(N_NODES + 63) / 64, 128, SMEM_PRE_BYTES>>>(x, pos, W1, b1);
    k_msg<<<GRID_MSG, 256, SMEM_MSG_BYTES>>>(ei, W2, b2);
    k_out<<<(N_NODES + 63) / 64, 128, SMEM_OUT_BYTES>>>(Wg, bg, out);
}

// round 11
// speedup vs baseline: 5.6598x; 1.3028x over previous
#include <cuda_runtime.h>
#include <cuda_bf16.h>
#include <cstdint>

#define N_NODES 50000
#define E_EDGES 1600000
#define M_TOTAL (E_EDGES + N_NODES)
#define NT16 (M_TOTAL / 16)            // 103125 warp-units (exact)
#define EU16  (E_EDGES / 16)           // 100000 (exact) — units >= this are self-loops
#define GRID_MSG 296

__device__ float g_agg[N_NODES * 64];
__device__ float g_YS[N_NODES * 64];   // x@W1[:32] + b1 + pos@W1[32:35]
__device__ float g_P[N_NODES * 64];    // pos@W1[32:35]
__device__ int g_ei_is64;
__device__ int g_tile;

// ---------------------------------------------------------------------------
__device__ __forceinline__ uint32_t smem_u32(const void* p) {
    uint32_t a;
    asm("{ .reg .u64 t; cvta.to.shared.u64 t, %1; cvt.u32.u64 %0, t; }" : "=r"(a) : "l"(p));
    return a;
}
__device__ __forceinline__ void ldsm4(uint32_t* r, uint32_t addr) {
    asm volatile("ldmatrix.sync.aligned.m8n8.x4.shared.b16 {%0,%1,%2,%3}, [%4];"
        : "=r"(r[0]), "=r"(r[1]), "=r"(r[2]), "=r"(r[3]) : "r"(addr));
}
__device__ __forceinline__ void mma_bf16(float* c, const uint32_t* a, uint32_t b0, uint32_t b1) {
    asm volatile("mma.sync.aligned.m16n8k16.row.col.f32.bf16.bf16.f32 "
        "{%0,%1,%2,%3}, {%4,%5,%6,%7}, {%8,%9}, {%0,%1,%2,%3};"
        : "+f"(c[0]), "+f"(c[1]), "+f"(c[2]), "+f"(c[3])
        : "r"(a[0]), "r"(a[1]), "r"(a[2]), "r"(a[3]), "r"(b0), "r"(b1));
}
__device__ __forceinline__ void split2(float a, float b, uint32_t& hi, uint32_t& lo) {
    __nv_bfloat162 h = __floats2bfloat162_rn(a, b);
    float ra = a - __bfloat162float(h.x);
    float rb = b - __bfloat162float(h.y);
    __nv_bfloat162 l = __floats2bfloat162_rn(ra, rb);
    hi = *(uint32_t*)&h; lo = *(uint32_t*)&l;
}

// ---------------------------------------------------------------------------
__global__ void k_detect(const int* __restrict__ ei_raw) {
    __shared__ int any_nonzero;
    if (threadIdx.x == 0) any_nonzero = 0;
    __syncthreads();
    int w = ei_raw[2 * threadIdx.x + 1];
    if (w != 0) atomicOr(&any_nonzero, 1);
    __syncthreads();
    if (threadIdx.x == 0) g_ei_is64 = any_nonzero ? 0 : 1;
}

__global__ void k_zero() {
    int i = blockIdx.x * blockDim.x + threadIdx.x;
    if (i == 0) g_tile = 0;
    if (i < N_NODES * 64 / 4)
        ((float4*)g_agg)[i] = make_float4(0.f, 0.f, 0.f, 0.f);
}

// ---------------------------------------------------------------------------
// k_pre: per node, fp32-exact:
//   Y1 = x @ W1[:32] + b1 ; P = pos @ W1[32:35] ; YS = Y1 + P
// ---------------------------------------------------------------------------
#define SPX 0
#define SPW (64 * 36)
#define SPT (SPW + 32 * 64)
#define SMEM_PRE_BYTES ((SPT + 192) * 4)

__global__ __launch_bounds__(128) void k_pre(
    const float* __restrict__ x, const float* __restrict__ pos,
    const float* __restrict__ W1, const float* __restrict__ b1)
{
    extern __shared__ float sm[];
    float* sX = sm + SPX;
    float* sW = sm + SPW;
    float* sWT = sm + SPT;
    const int tid = threadIdx.x;
    const int nbase = blockIdx.x * 64;

    for (int i = tid; i < 32 * 16; i += 128)
        ((float4*)sW)[i] = __ldg((const float4*)W1 + i);
    if (tid < 64) {
        sWT[tid]       = W1[32 * 64 + tid];
        sWT[64 + tid]  = W1[33 * 64 + tid];
        sWT[128 + tid] = W1[34 * 64 + tid];
    }
    for (int idx = tid; idx < 64 * 8; idx += 128) {
        int r = idx >> 3, c4 = idx & 7;
        float4 v = make_float4(0.f, 0.f, 0.f, 0.f);
        if (nbase + r < N_NODES)
            v = *(const float4*)(x + (size_t)(nbase + r) * 32 + c4 * 4);
        *(float4*)(sX + r * 36 + c4 * 4) = v;
    }
    __syncthreads();

    const int tx = tid & 7, ty = tid >> 3;
    const int fbase = tx * 8;
    float acc[4][8];
    float bj[8];
    #pragma unroll
    for (int j = 0; j < 8; j++) bj[j] = __ldg(&b1[fbase + j]);
    #pragma unroll
    for (int i = 0; i < 4; i++)
        #pragma unroll
        for (int j = 0; j < 8; j++) acc[i][j] = bj[j];

    for (int k4 = 0; k4 < 8; k4++) {
        const int k0 = k4 * 4;
        float4 wv[4][2];
        #pragma unroll
        for (int kk = 0; kk < 4; kk++) {
            wv[kk][0] = *(const float4*)(sW + (k0 + kk) * 64 + fbase);
            wv[kk][1] = *(const float4*)(sW + (k0 + kk) * 64 + fbase + 4);
        }
        #pragma unroll
        for (int i = 0; i < 4; i++) {
            float4 av = *(const float4*)(sX + (ty + 16 * i) * 36 + k0);
            float a4[4] = {av.x, av.y, av.z, av.w};
            #pragma unroll
            for (int kk = 0; kk < 4; kk++) {
                const float* w = &wv[kk][0].x;
                #pragma unroll
                for (int j = 0; j < 8; j++)
                    acc[i][j] = fmaf(a4[kk], w[j], acc[i][j]);
            }
        }
    }
    #pragma unroll
    for (int i = 0; i < 4; i++) {
        int n = nbase + ty + 16 * i;
        if (n < N_NODES) {
            float p0 = pos[n * 3 + 0], p1 = pos[n * 3 + 1], p2 = pos[n * 3 + 2];
            float pv[8], ys[8];
            #pragma unroll
            for (int j = 0; j < 8; j++) {
                int c = fbase + j;
                pv[j] = fmaf(p0, sWT[c], fmaf(p1, sWT[64 + c], p2 * sWT[128 + c]));
                ys[j] = acc[i][j] + pv[j];
            }
            *(float4*)(g_YS + (size_t)n * 64 + fbase)     = make_float4(ys[0], ys[1], ys[2], ys[3]);
            *(float4*)(g_YS + (size_t)n * 64 + fbase + 4) = make_float4(ys[4], ys[5], ys[6], ys[7]);
            *(float4*)(g_P  + (size_t)n * 64 + fbase)     = make_float4(pv[0], pv[1], pv[2], pv[3]);
            *(float4*)(g_P  + (size_t)n * 64 + fbase + 4) = make_float4(pv[4], pv[5], pv[6], pv[7]);
        }
    }
}

// ---------------------------------------------------------------------------
// k_msg: warp-autonomous. Each warp steals 16-message units and runs the full
// pipeline (index load -> gather relu(YS[src]-P[dst]) -> split -> bf16 3-pass
// GEMM -> relu -> atomicMax) with only __syncwarp ordering. No block barriers
// after the initial W2 staging.
// smem: W2_HI | W2_LO | B2 | per-warp H1 blocks (4608 B each; sOut aliases).
// ---------------------------------------------------------------------------
#define O_W2_HI  0                      // 64 x 36 words = 9216 B
#define O_W2_LO  9216
#define O_B2     18432                  // 64 fp32
#define O_H1     18688                  // 8 warps x 4608 B (HI 2304 | LO 2304)
#define SMEM_MSG_BYTES (18688 + 8 * 4608)   // 55552

__global__ __launch_bounds__(256, 2) void k_msg(
    const void* __restrict__ ei_raw,
    const float* __restrict__ W2, const float* __restrict__ bias2)
{
    extern __shared__ char smc[];
    const uint32_t smb = smem_u32(smc);
    uint32_t* W2_HI = (uint32_t*)(smc + O_W2_HI);
    uint32_t* W2_LO = (uint32_t*)(smc + O_W2_LO);
    float* sB2 = (float*)(smc + O_B2);

    const int tid = threadIdx.x;
    const int wid = tid >> 5;
    const int lid = tid & 31;

    // ---- stage W2^T split + b2 (once per CTA) ----
    for (int i = tid; i < 64 * 32; i += 256) {
        int n = i / 32, w = i % 32, k = 2 * w;
        uint32_t hi, lo; split2(W2[k * 64 + n], W2[(k + 1) * 64 + n], hi, lo);
        W2_HI[n * 36 + w] = hi; W2_LO[n * 36 + w] = lo;
    }
    if (tid < 64) sB2[tid] = bias2[tid];
    const int is64 = g_ei_is64;
    __syncthreads();   // last block barrier

    // warp-private H1 block (sOut aliases it after GEMM)
    const uint32_t h1w = smb + O_H1 + wid * 4608;          // HI base (bytes)
    float* sOutW = (float*)(smc + O_H1 + wid * 4608);

    // lane roles
    const int q    = lid & 15;           // index-load: message within unit
    const int half = lid >> 4;           // 0 = src, 1 = dst
    const int gb_m = lid >> 4;           // gather: msg within pair
    const int gb_h = (lid >> 3) & 1;     //         half-row
    const int gb_s = lid & 7;            //         16B segment
    const int arow  = lid & 15;
    const int akoff = (lid >> 4) * 8;
    const int bnrow = (lid & 7) + ((lid & 16) ? 8 : 0);
    const int bk = ((lid >> 3) & 1) * 8;
    const int cq = lid & 3;

    for (;;) {
        int u;
        if (lid == 0) u = atomicAdd(&g_tile, 1);
        u = __shfl_sync(0xffffffffu, u, 0);
        if (u >= NT16) break;

        // ---- index load: lanes 0-15 src, 16-31 dst (held in idxv) ----
        int idxv;
        {
            int m = u * 16 + q;
            if (u < EU16) {
                if (is64) idxv = (int)((const long long*)ei_raw)[(size_t)half * E_EDGES + m];
                else      idxv = ((const int*)ei_raw)[(size_t)half * E_EDGES + m];
                if ((unsigned)idxv >= N_NODES) idxv = 0;
            } else {
                idxv = m - E_EDGES;      // self-loop: src = dst
            }
        }

        // ---- gather: relu(YS[src] - P[dst]) -> split -> warp-private H1 ----
        #pragma unroll
        for (int it = 0; it < 8; it++) {
            int j = it * 2 + gb_m;
            int src = __shfl_sync(0xffffffffu, idxv, j);
            int dst = __shfl_sync(0xffffffffu, idxv, 16 + j);
            int n0 = gb_h * 32 + gb_s * 4;
            float4 ys = __ldg((const float4*)(g_YS + (size_t)src * 64 + n0));
            float4 pp = __ldg((const float4*)(g_P  + (size_t)dst * 64 + n0));
            float v0 = fmaxf(ys.x - pp.x, 0.f);
            float v1 = fmaxf(ys.y - pp.y, 0.f);
            float v2 = fmaxf(ys.z - pp.z, 0.f);
            float v3 = fmaxf(ys.w - pp.w, 0.f);
            uint32_t a, b, c, d;
            split2(v0, v1, a, b);
            split2(v2, v3, c, d);
            uint32_t wb = h1w + j * 144 + gb_h * 64 + gb_s * 8;
            *(uint2*)(size_t)0;  // (no-op placeholder removed below)
            *((uint2*)(smc + (wb - smb)))          = make_uint2(a, c);
            *((uint2*)(smc + (wb - smb) + 2304))   = make_uint2(b, d);
        }
        __syncwarp();

        // ---- GEMM: out = relu(H1 @ W2^T + b2), K=64, bf16 3-pass ----
        float acc[8][4];
        #pragma unroll
        for (int nb = 0; nb < 8; nb++) {
            int c = 8 * nb + 2 * cq;
            acc[nb][0] = sB2[c]; acc[nb][1] = sB2[c + 1];
            acc[nb][2] = sB2[c]; acc[nb][3] = sB2[c + 1];
        }
        #pragma unroll
        for (int kc = 0; kc < 4; kc++) {
            const int k0 = kc * 16;
            uint32_t ahi[4], alo[4];
            uint32_t aaddr = h1w + arow * 144 + (k0 + akoff) * 2;
            ldsm4(ahi, aaddr);
            ldsm4(alo, aaddr + 2304);
            #pragma unroll
            for (int hf = 0; hf < 4; hf++) {
                uint32_t bhi[4], blo[4];
                uint32_t baddr = smb + O_W2_HI + (hf * 16 + bnrow) * 144 + (k0 + bk) * 2;
                ldsm4(bhi, baddr);
                ldsm4(blo, baddr + (O_W2_LO - O_W2_HI));
                int n0 = hf * 2, n1 = hf * 2 + 1;
                mma_bf16(acc[n0], ahi, bhi[0], bhi[1]);
                mma_bf16(acc[n1], ahi, bhi[2], bhi[3]);
                mma_bf16(acc[n0], alo, bhi[0], bhi[1]);
                mma_bf16(acc[n1], alo, bhi[2], bhi[3]);
                mma_bf16(acc[n0], ahi, blo[0], blo[1]);
                mma_bf16(acc[n1], ahi, blo[2], blo[3]);
            }
        }
        __syncwarp();   // all ldsm reads of H1 done before sOut (alias) writes

        // ---- epilogue: relu -> sOutW (fp32, stride 66, warp-private) ----
        {
            int rA = lid >> 2;
            #pragma unroll
            for (int nb = 0; nb < 8; nb++) {
                int c = 8 * nb + 2 * cq;
                *(float2*)(sOutW + rA * 66 + c) =
                    make_float2(fmaxf(acc[nb][0], 0.f), fmaxf(acc[nb][1], 0.f));
                *(float2*)(sOutW + (rA + 8) * 66 + c) =
                    make_float2(fmaxf(acc[nb][2], 0.f), fmaxf(acc[nb][3], 0.f));
            }
        }
        __syncwarp();

        // ---- coalesced predicated max scatter (1 line per REDG) ----
        #pragma unroll
        for (int j = 0; j < 16; j++) {
            int dst = __shfl_sync(0xffffffffu, idxv, 16 + j);
            float v0 = sOutW[j * 66 + lid];
            float v1 = sOutW[j * 66 + 32 + lid];
            int* ap = (int*)g_agg + (size_t)dst * 64;
            if (v0 > 0.f) atomicMax(ap + lid,      __float_as_int(v0));
            if (v1 > 0.f) atomicMax(ap + 32 + lid, __float_as_int(v1));
        }
        __syncwarp();   // sOut reads done before next unit's gather overwrites
    }
}

// ---------------------------------------------------------------------------
// k_out: out = agg @ Wg + bg    [50000,64] x [64,128]
// ---------------------------------------------------------------------------
#define SMO_A 0
#define SMO_W (64 * 68)
#define SMEM_OUT_BYTES ((64 * 68 + 64 * 128) * 4)

__global__ __launch_bounds__(128) void k_out(
    const float* __restrict__ Wg, const float* __restrict__ bg,
    float* __restrict__ out)
{
    extern __shared__ float sm[];
    float* sA = sm + SMO_A;
    float* sW = sm + SMO_W;
    const int tid = threadIdx.x;
    const int nbase = blockIdx.x * 64;

    {
        float4* dst4 = (float4*)sW;
        const float4* src4 = (const float4*)Wg;
        for (int i = tid; i < 64 * 32; i += 128) dst4[i] = __ldg(src4 + i);
    }
    for (int idx = tid; idx < 64 * 16; idx += 128) {
        int rr = idx >> 4, c4 = idx & 15;
        float4 v = make_float4(0.f, 0.f, 0.f, 0.f);
        if (nbase + rr < N_NODES)
            v = *(const float4*)(g_agg + (size_t)(nbase + rr) * 64 + c4 * 4);
        *(float4*)(sA + rr * 68 + c4 * 4) = v;
    }
    __syncthreads();

    const int tx = tid & 15;
    const int ty = tid >> 4;
    const int fbase = tx * 8;

    float acc[8][8];
    float bj[8];
    #pragma unroll
    for (int j = 0; j < 8; j++) bj[j] = __ldg(&bg[fbase + j]);
    #pragma unroll
    for (int i = 0; i < 8; i++)
        #pragma unroll
        for (int j = 0; j < 8; j++) acc[i][j] = bj[j];

    for (int k4 = 0; k4 < 16; k4++) {
        const int k0 = k4 * 4;
        float4 wv[4][2];
        #pragma unroll
        for (int kk = 0; kk < 4; kk++) {
            wv[kk][0] = *(const float4*)(sW + (k0 + kk) * 128 + fbase);
            wv[kk][1] = *(const float4*)(sW + (k0 + kk) * 128 + fbase + 4);
        }
        #pragma unroll
        for (int i = 0; i < 8; i++) {
            float4 av = *(const float4*)(sA + (ty + 8 * i) * 68 + k0);
            float a4[4] = {av.x, av.y, av.z, av.w};
            #pragma unroll
            for (int kk = 0; kk < 4; kk++) {
                const float* w = &wv[kk][0].x;
                #pragma unroll
                for (int j = 0; j < 8; j++)
                    acc[i][j] = fmaf(a4[kk], w[j], acc[i][j]);
            }
        }
    }

    #pragma unroll
    for (int i = 0; i < 8; i++) {
        int n = nbase + ty + 8 * i;
        if (n < N_NODES) {
            float4 v0, v1;
            v0.x = acc[i][0]; v0.y = acc[i][1]; v0.z = acc[i][2]; v0.w = acc[i][3];
            v1.x = acc[i][4]; v1.y = acc[i][5]; v1.z = acc[i][6]; v1.w = acc[i][7];
            *(float4*)(out + (size_t)n * 128 + fbase)     = v0;
            *(float4*)(out + (size_t)n * 128 + fbase + 4) = v1;
        }
    }
}

// ---------------------------------------------------------------------------
extern "C" void kernel_launch(void* const* d_in, const int* in_sizes, int n_in,
                              void* d_out, int out_size) {
    const float* x   = (const float*)d_in[0];
    const float* pos = (const float*)d_in[1];
    const void*  ei  = d_in[2];
    const float* W1  = (const float*)d_in[3];
    const float* b1  = (const float*)d_in[4];
    const float* W2  = (const float*)d_in[5];
    const float* b2  = (const float*)d_in[6];
    const float* Wg  = (const float*)d_in[7];
    const float* bg  = (const float*)d_in[8];
    float* out = (float*)d_out;

    cudaFuncSetAttribute(k_msg, cudaFuncAttributeMaxDynamicSharedMemorySize, SMEM_MSG_BYTES);
    cudaFuncSetAttribute(k_out, cudaFuncAttributeMaxDynamicSharedMemorySize, SMEM_OUT_BYTES);
    cudaFuncSetAttribute(k_pre, cudaFuncAttributeMaxDynamicSharedMemorySize, SMEM_PRE_BYTES);

    k_detect<<<1, 1024>>>((const int*)ei);
    k_zero<<<(N_NODES * 64 / 4 + 255) / 256, 256>>>();
    k_pre<<<(N_NODES + 63) / 64, 128, SMEM_PRE_BYTES>>>(x, pos, W1, b1);
    k_msg<<<GRID_MSG, 256, SMEM_MSG_BYTES>>>(ei, W2, b2);
    k_out<<<(N_NODES + 63) / 64, 128, SMEM_OUT_BYTES>>>(Wg, bg, out);
}